// round 1
// baseline (speedup 1.0000x reference)
#include <cuda_runtime.h>
#include <math.h>

// YoloLoss for fixed problem shape: input [32,255,76,76] f32, targets [32,20,5] f32, l int32.
// Strategy: read only channels 0..4 everywhere (11MB instead of 188MB), gather the 80
// class channels only at obj cells, fuse target-matching + ignore-mask into a single
// 20-iteration per-cell loop. Double accumulators for the 5 global sums.

#define IN_H 76
#define IN_W 76
#define HW   (IN_H * IN_W)        // 5776
#define BS   32
#define NT   20
#define NCLS 80
#define CEPS 1e-7f

// accumulators: 0=n_obj, 1=loc_sum, 2=cls_sum, 3=conf_num, 4=conf_mask_sum
__device__ double g_acc[5];

__constant__ float c_anchors[18] = {12,16, 19,36, 40,28, 36,75, 76,55,
                                    72,146, 142,110, 192,243, 459,401};

__global__ void yolo_init() {
    if (threadIdx.x < 5) g_acc[threadIdx.x] = 0.0;
}

__device__ __forceinline__ float warp_sum(float v) {
    #pragma unroll
    for (int o = 16; o; o >>= 1) v += __shfl_down_sync(0xffffffffu, v, o);
    return v;
}

__device__ __forceinline__ float sigmoidf_(float x) {
    return 1.0f / (1.0f + expf(-x));
}

__global__ void __launch_bounds__(256, 4)
yolo_main(const float* __restrict__ inp, const float* __restrict__ tgt,
          const int* __restrict__ lptr)
{
    __shared__ float s_gx[NT], s_gy[NT], s_gw[NT], s_gh[NT];
    __shared__ int   s_k[NT], s_gi[NT], s_gj[NT], s_cls[NT], s_valid[NT];
    __shared__ float s_aw[3], s_ah[3];
    __shared__ int   s_l;
    __shared__ double s_acc[5];

    const int b   = blockIdx.y;
    const int tid = threadIdx.x;

    if (tid == 0) s_l = lptr[0];
    if (tid < 5)  s_acc[tid] = 0.0;
    __syncthreads();
    const int l  = s_l;
    const int m0 = 6 - 3 * l;     // ANCHORS_MASK[l][0]

    if (tid < 3) {
        s_aw[tid] = c_anchors[2 * (m0 + tid)]     * 0.125f;   // stride = 608/76 = 8
        s_ah[tid] = c_anchors[2 * (m0 + tid) + 1] * 0.125f;
    }
    if (tid < NT) {
        const float* tp = tgt + ((size_t)b * NT + tid) * 5;
        float gx = tp[0] * (float)IN_W;
        float gy = tp[1] * (float)IN_H;
        float gw = tp[2] * (float)IN_W;
        float gh = tp[3] * (float)IN_H;
        int cls  = (int)tp[4];
        // argmax over 9 anchors of zero-centered wh IoU (first max wins, like jnp.argmax)
        float best = -1.0f; int bn = 0;
        #pragma unroll
        for (int a = 0; a < 9; a++) {
            float aw = c_anchors[2*a] * 0.125f, ah = c_anchors[2*a+1] * 0.125f;
            float inter = fminf(gw, aw) * fminf(gh, ah);
            float uni   = gw * gh + aw * ah - inter;
            float r = inter / uni;
            if (r > best) { best = r; bn = a; }
        }
        int k = bn - m0;
        s_gx[tid] = gx; s_gy[tid] = gy; s_gw[tid] = gw; s_gh[tid] = gh;
        s_k[tid] = k;
        s_valid[tid] = (k >= 0 && k < 3) ? 1 : 0;
        int gi = (int)floorf(gx); gi = min(max(gi, 0), IN_W - 1);
        int gj = (int)floorf(gy); gj = min(max(gj, 0), IN_H - 1);
        s_gi[tid] = gi; s_gj[tid] = gj; s_cls[tid] = cls;
    }
    __syncthreads();

    const int m = blockIdx.x * blockDim.x + tid;   // cell within batch: k*HW + j*W + i
    float loc = 0.f, clsl = 0.f, confn = 0.f, cmask = 0.f, objf = 0.f;

    if (m < 3 * HW) {
        const int k   = m / HW;
        const int rem = m - k * HW;
        const int j   = rem / IN_W;
        const int i   = rem - j * IN_W;

        const float* base = inp + ((size_t)b * 255 + (size_t)k * 85) * HW + rem;
        float xr = base[0 * HW];
        float yr = base[1 * HW];
        float wr = base[2 * HW];
        float hr = base[3 * HW];
        float cr = base[4 * HW];

        const float px = (float)i + sigmoidf_(xr);
        const float py = (float)j + sigmoidf_(yr);
        const float pw = expf(wr) * s_aw[k];
        const float ph = expf(hr) * s_ah[k];

        const float p_minx = px - pw * 0.5f, p_maxx = px + pw * 0.5f;
        const float p_miny = py - ph * 0.5f, p_maxy = py + ph * 0.5f;
        const float pa = pw * ph;

        float best_iou = 0.0f;   // ious are >= 0
        int   tm = -1;           // last matching target wins (scatter-set semantics)
        #pragma unroll
        for (int t = 0; t < NT; t++) {
            float gx = s_gx[t], gy = s_gy[t], gw = s_gw[t], gh = s_gh[t];
            float iw = fminf(gx + gw*0.5f, p_maxx) - fmaxf(gx - gw*0.5f, p_minx);
            float ih = fminf(gy + gh*0.5f, p_maxy) - fmaxf(gy - gh*0.5f, p_miny);
            iw = fmaxf(iw, 0.f); ih = fmaxf(ih, 0.f);
            float inter = iw * ih;
            float iou = inter / (gw * gh + pa - inter);
            best_iou = fmaxf(best_iou, iou);
            if (s_valid[t] && s_k[t] == k && s_gi[t] == i && s_gj[t] == j) tm = t;
        }

        const float obj = (tm >= 0) ? 1.0f : 0.0f;
        objf = obj;

        // conf BCE with mask = obj || best_iou <= 0.5
        {
            float conf = sigmoidf_(cr);
            float p = fminf(fmaxf(conf, CEPS), 1.0f - CEPS);
            float bce = -obj * logf(p) - (1.0f - obj) * logf(1.0f - p);
            float cm = (tm >= 0 || best_iou <= 0.5f) ? 1.0f : 0.0f;
            confn = cm * bce;
            cmask = cm;
        }

        if (tm >= 0) {
            // CIoU(pred_box, gt_box), exactly mirroring the reference clips
            float gx = s_gx[tm], gy = s_gy[tm], gw = s_gw[tm], gh = s_gh[tm];
            float g_minx = gx - gw*0.5f, g_maxx = gx + gw*0.5f;
            float g_miny = gy - gh*0.5f, g_maxy = gy + gh*0.5f;
            float iw = fmaxf(fminf(g_maxx, p_maxx) - fmaxf(g_minx, p_minx), 0.f);
            float ih = fmaxf(fminf(g_maxy, p_maxy) - fmaxf(g_miny, p_miny), 0.f);
            float inter = iw * ih;
            float uni   = fmaxf(pa + gw * gh - inter, 1e-6f);
            float iou   = inter / uni;
            float dx = px - gx, dy = py - gy;
            float cd = dx * dx + dy * dy;
            float ew = fmaxf(fmaxf(g_maxx, p_maxx) - fminf(g_minx, p_minx), 0.f);
            float eh = fmaxf(fmaxf(g_maxy, p_maxy) - fminf(g_miny, p_miny), 0.f);
            float ed = fmaxf(ew * ew + eh * eh, 1e-6f);
            float da = atanf(pw / fmaxf(ph, 1e-6f)) - atanf(gw / fmaxf(gh, 1e-6f));
            float v  = 0.405284734569351f * da * da;  // 4/pi^2
            float alpha = v / fmaxf(1.0f - iou + v, 1e-6f);
            float ciou = iou - cd / ed - alpha * v;
            loc = 1.0f - ciou;

            // class BCE: gather the 80 class channels only here
            int cc = s_cls[tm];
            float cs = 0.0f;
            #pragma unroll 8
            for (int c = 0; c < NCLS; c++) {
                float pc = sigmoidf_(base[(size_t)(5 + c) * HW]);
                pc = fminf(fmaxf(pc, CEPS), 1.0f - CEPS);
                float tt = (c == cc) ? 1.0f : 0.0f;
                cs += -tt * logf(pc) - (1.0f - tt) * logf(1.0f - pc);
            }
            clsl = cs;
        }
    }

    // reduce 5 values: warp shuffle -> shared double -> global double
    float vals[5] = {objf, loc, clsl, confn, cmask};
    const int lane = tid & 31;
    #pragma unroll
    for (int q = 0; q < 5; q++) {
        float v = warp_sum(vals[q]);
        if (lane == 0 && v != 0.0f) atomicAdd(&s_acc[q], (double)v);
    }
    __syncthreads();
    if (tid < 5) {
        double v = s_acc[tid];
        if (v != 0.0) atomicAdd(&g_acc[tid], v);
    }
}

__global__ void yolo_final(float* __restrict__ out, const int* __restrict__ lptr)
{
    const int l = lptr[0];
    double n_obj = g_acc[0]; if (n_obj < 1.0) n_obj = 1.0;
    double cms   = g_acc[4]; if (cms   < 1.0) cms   = 1.0;
    const double balance = (l == 0) ? 0.4 : (l == 1 ? 1.0 : 4.0);
    const double obj_ratio = 5.0 * 608.0 * 608.0 / (416.0 * 416.0);
    const double box_ratio = 0.05;
    const double cls_ratio = 1.0;   // 80/80

    double loss = g_acc[1] / n_obj * box_ratio
                + g_acc[3] / cms * balance * obj_ratio
                + g_acc[2] / (n_obj * (double)NCLS) * cls_ratio;
    out[0] = (float)loss;
}

extern "C" void kernel_launch(void* const* d_in, const int* in_sizes, int n_in,
                              void* d_out, int out_size)
{
    const float* inp  = (const float*)d_in[0];
    const float* tgt  = (const float*)d_in[1];
    const int*   lptr = (const int*)d_in[2];
    float* out = (float*)d_out;

    const int bs = in_sizes[0] / (255 * HW);   // 32
    const int blocks_x = (3 * HW + 255) / 256; // 68

    yolo_init<<<1, 32>>>();
    yolo_main<<<dim3(blocks_x, bs), 256>>>(inp, tgt, lptr);
    yolo_final<<<1, 1>>>(out, lptr);
}

// round 2
// speedup vs baseline: 1.1634x; 1.1634x over previous
#include <cuda_runtime.h>
#include <math.h>

// YoloLoss, fixed shape: input [32,255,76,76] f32, targets [32,20,5] f32, l int32.
// Single fused kernel: per-cell decode + 20-target ignore/match loop (fast-math
// intrinsics), per-block partial sums, last-block finalize. Rare obj-cell path
// (CIoU + 80-class BCE) uses accurate math.

#define IN_H 76
#define IN_W 76
#define HW   (IN_H * IN_W)        // 5776
#define NT   20
#define NCLS 80
#define CEPS 1e-7f
#define MAXB 4096

// per-block partials: 0=n_obj, 1=loc_sum, 2=cls_sum, 3=conf_num, 4=conf_mask_sum
__device__ double g_part[MAXB][5];
__device__ unsigned g_count = 0;

__constant__ float c_anchors[18] = {12,16, 19,36, 40,28, 36,75, 76,55,
                                    72,146, 142,110, 192,243, 459,401};

__device__ __forceinline__ float warp_sum(float v) {
    #pragma unroll
    for (int o = 16; o; o >>= 1) v += __shfl_down_sync(0xffffffffu, v, o);
    return v;
}
__device__ __forceinline__ double warp_sumd(double v) {
    #pragma unroll
    for (int o = 16; o; o >>= 1) v += __shfl_down_sync(0xffffffffu, v, o);
    return v;
}

// fast sigmoid (MUFU.EX2 + MUFU.RCP)
__device__ __forceinline__ float fsig(float x) {
    return __frcp_rn(1.0f + __expf(-x));
}

__global__ void __launch_bounds__(256, 4)
yolo_fused(const float* __restrict__ inp, const float* __restrict__ tgt,
           const int* __restrict__ lptr, float* __restrict__ out)
{
    // per-target precomputed data
    __shared__ float4 s_mm[NT];          // minx, maxx, miny, maxy
    __shared__ float  s_area[NT];
    __shared__ int    s_tcell[NT];       // flat cell id (k*HW + j*W + i) or -1
    __shared__ float  s_cx[NT], s_cy[NT], s_w[NT], s_h[NT];
    __shared__ int    s_cls[NT];
    __shared__ float  s_aw[3], s_ah[3];
    __shared__ int    s_l;
    __shared__ double s_acc[5];
    __shared__ int    s_islast;

    const int b   = blockIdx.y;
    const int tid = threadIdx.x;

    if (tid == 0) s_l = lptr[0];
    if (tid < 5)  s_acc[tid] = 0.0;
    __syncthreads();
    const int m0 = 6 - 3 * s_l;           // ANCHORS_MASK[l][0]

    if (tid < 3) {
        s_aw[tid] = c_anchors[2 * (m0 + tid)]     * 0.125f;   // stride = 608/76 = 8
        s_ah[tid] = c_anchors[2 * (m0 + tid) + 1] * 0.125f;
    }
    if (tid < NT) {
        const float* tp = tgt + ((size_t)b * NT + tid) * 5;
        float gx = tp[0] * (float)IN_W;
        float gy = tp[1] * (float)IN_H;
        float gw = tp[2] * (float)IN_W;
        float gh = tp[3] * (float)IN_H;
        // argmax over 9 anchors of zero-centered wh IoU (first max wins)
        float best = -1.0f; int bn = 0;
        #pragma unroll
        for (int a = 0; a < 9; a++) {
            float aw = c_anchors[2*a] * 0.125f, ah = c_anchors[2*a+1] * 0.125f;
            float inter = fminf(gw, aw) * fminf(gh, ah);
            float r = inter / (gw * gh + aw * ah - inter);
            if (r > best) { best = r; bn = a; }
        }
        int k = bn - m0;
        int gi = (int)floorf(gx); gi = min(max(gi, 0), IN_W - 1);
        int gj = (int)floorf(gy); gj = min(max(gj, 0), IN_H - 1);
        s_tcell[tid] = (k >= 0 && k < 3) ? (k * HW + gj * IN_W + gi) : -1;
        s_mm[tid] = make_float4(gx - gw * 0.5f, gx + gw * 0.5f,
                                gy - gh * 0.5f, gy + gh * 0.5f);
        s_area[tid] = gw * gh;
        s_cx[tid] = gx; s_cy[tid] = gy; s_w[tid] = gw; s_h[tid] = gh;
        s_cls[tid] = (int)tp[4];
    }
    __syncthreads();

    const int m = blockIdx.x * blockDim.x + tid;   // cell within batch
    float loc = 0.f, clsl = 0.f, confn = 0.f, cmask = 0.f, objf = 0.f;

    if (m < 3 * HW) {
        const int k   = m / HW;
        const int rem = m - k * HW;
        const int j   = rem / IN_W;
        const int i   = rem - j * IN_W;

        const float* base = inp + ((size_t)b * 255 + (size_t)k * 85) * HW + rem;
        const float xr = base[0 * HW];
        const float yr = base[1 * HW];
        const float wr = base[2 * HW];
        const float hr = base[3 * HW];
        const float cr = base[4 * HW];

        const float px = (float)i + fsig(xr);
        const float py = (float)j + fsig(yr);
        const float pw = __expf(wr) * s_aw[k];
        const float ph = __expf(hr) * s_ah[k];

        const float p_minx = px - pw * 0.5f, p_maxx = px + pw * 0.5f;
        const float p_miny = py - ph * 0.5f, p_maxy = py + ph * 0.5f;
        const float pa = pw * ph;

        float best_iou = 0.0f;
        int   tm = -1;                   // last matching target wins
        #pragma unroll
        for (int t = 0; t < NT; t++) {
            float4 mm = s_mm[t];
            float iw = fmaxf(fminf(mm.y, p_maxx) - fmaxf(mm.x, p_minx), 0.f);
            float ih = fmaxf(fminf(mm.w, p_maxy) - fmaxf(mm.z, p_miny), 0.f);
            float inter = iw * ih;
            float iou = __fdividef(inter, s_area[t] + pa - inter);
            best_iou = fmaxf(best_iou, iou);
            if (s_tcell[t] == m) tm = t;
        }

        const float obj = (tm >= 0) ? 1.0f : 0.0f;
        objf = obj;

        // conf BCE with mask = obj || best_iou <= 0.5
        {
            float p = fsig(cr);
            p = fminf(fmaxf(p, CEPS), 1.0f - CEPS);
            float bce = -obj * __logf(p) - (1.0f - obj) * __logf(1.0f - p);
            float cm = (tm >= 0 || best_iou <= 0.5f) ? 1.0f : 0.0f;
            confn = cm * bce;
            cmask = cm;
        }

        if (tm >= 0) {
            // rare path: CIoU + 80-class BCE (accurate math)
            float gx = s_cx[tm], gy = s_cy[tm], gw = s_w[tm], gh = s_h[tm];
            float g_minx = gx - gw*0.5f, g_maxx = gx + gw*0.5f;
            float g_miny = gy - gh*0.5f, g_maxy = gy + gh*0.5f;
            float iw = fmaxf(fminf(g_maxx, p_maxx) - fmaxf(g_minx, p_minx), 0.f);
            float ih = fmaxf(fminf(g_maxy, p_maxy) - fmaxf(g_miny, p_miny), 0.f);
            float inter = iw * ih;
            float uni   = fmaxf(pa + gw * gh - inter, 1e-6f);
            float iou   = inter / uni;
            float dx = px - gx, dy = py - gy;
            float cd = dx * dx + dy * dy;
            float ew = fmaxf(fmaxf(g_maxx, p_maxx) - fminf(g_minx, p_minx), 0.f);
            float eh = fmaxf(fmaxf(g_maxy, p_maxy) - fminf(g_miny, p_miny), 0.f);
            float ed = fmaxf(ew * ew + eh * eh, 1e-6f);
            float da = atanf(pw / fmaxf(ph, 1e-6f)) - atanf(gw / fmaxf(gh, 1e-6f));
            float v  = 0.405284734569351f * da * da;  // 4/pi^2
            float alpha = v / fmaxf(1.0f - iou + v, 1e-6f);
            loc = 1.0f - (iou - cd / ed - alpha * v);

            int cc = s_cls[tm];
            float cs = 0.0f;
            #pragma unroll 8
            for (int c = 0; c < NCLS; c++) {
                float pc = fsig(base[(size_t)(5 + c) * HW]);
                pc = fminf(fmaxf(pc, CEPS), 1.0f - CEPS);
                cs += (c == cc) ? -logf(pc) : -logf(1.0f - pc);
            }
            clsl = cs;
        }
    }

    // block reduction: warp shuffle -> shared double
    float vals[5] = {objf, loc, clsl, confn, cmask};
    const int lane = tid & 31;
    #pragma unroll
    for (int q = 0; q < 5; q++) {
        float v = warp_sum(vals[q]);
        if (lane == 0 && v != 0.0f) atomicAdd(&s_acc[q], (double)v);
    }
    __syncthreads();

    const int nblocks = gridDim.x * gridDim.y;
    const int bid = blockIdx.y * gridDim.x + blockIdx.x;
    if (tid < 5) g_part[bid][tid] = s_acc[tid];

    // last-block finalize
    if (tid == 0) {
        __threadfence();
        unsigned v = atomicAdd(&g_count, 1u);
        s_islast = (v == (unsigned)(nblocks - 1));
        if (s_islast) g_count = 0;     // self-reset -> graph-replay deterministic
    }
    __syncthreads();
    if (!s_islast) return;

    double acc[5] = {0, 0, 0, 0, 0};
    for (int r = tid; r < nblocks; r += blockDim.x) {
        #pragma unroll
        for (int q = 0; q < 5; q++) acc[q] += g_part[r][q];
    }
    __shared__ double s_fin[5];
    if (tid < 5) s_fin[tid] = 0.0;
    __syncthreads();
    #pragma unroll
    for (int q = 0; q < 5; q++) {
        double v = warp_sumd(acc[q]);
        if (lane == 0 && v != 0.0) atomicAdd(&s_fin[q], v);
    }
    __syncthreads();
    if (tid == 0) {
        double n_obj = s_fin[0] < 1.0 ? 1.0 : s_fin[0];
        double cms   = s_fin[4] < 1.0 ? 1.0 : s_fin[4];
        const int l = s_l;
        const double balance = (l == 0) ? 0.4 : (l == 1 ? 1.0 : 4.0);
        const double obj_ratio = 5.0 * 608.0 * 608.0 / (416.0 * 416.0);
        double loss = s_fin[1] / n_obj * 0.05
                    + s_fin[3] / cms * balance * obj_ratio
                    + s_fin[2] / (n_obj * (double)NCLS);
        out[0] = (float)loss;
    }
}

extern "C" void kernel_launch(void* const* d_in, const int* in_sizes, int n_in,
                              void* d_out, int out_size)
{
    const float* inp  = (const float*)d_in[0];
    const float* tgt  = (const float*)d_in[1];
    const int*   lptr = (const int*)d_in[2];
    float* out = (float*)d_out;

    const int bs = in_sizes[0] / (255 * HW);   // 32
    const int blocks_x = (3 * HW + 255) / 256; // 68

    yolo_fused<<<dim3(blocks_x, bs), 256>>>(inp, tgt, lptr, out);
}

// round 3
// speedup vs baseline: 2.0435x; 1.7565x over previous
#include <cuda_runtime.h>
#include <math.h>

// YoloLoss, fixed shape: input [32,255,76,76] f32, targets [32,20,5] f32, l int32.
// R3: 4 cells/thread (float4 loads; quads never cross channel/row since HW,76 % 4 == 0),
// division-free ignore test (iou>0.5 <=> 3*inter > ga+pa), single fused kernel with
// last-block finalize.

#define IN_H 76
#define IN_W 76
#define HW   (IN_H * IN_W)        // 5776
#define NT   20
#define NCLS 80
#define CEPS 1e-7f
#define MAXB 1024

// per-block partials: 0=n_obj, 1=loc_sum, 2=cls_sum, 3=conf_num, 4=conf_mask_sum
__device__ double g_part[MAXB][5];
__device__ unsigned g_count = 0;

__constant__ float c_anchors[18] = {12,16, 19,36, 40,28, 36,75, 76,55,
                                    72,146, 142,110, 192,243, 459,401};

__device__ __forceinline__ float warp_sum(float v) {
    #pragma unroll
    for (int o = 16; o; o >>= 1) v += __shfl_down_sync(0xffffffffu, v, o);
    return v;
}
__device__ __forceinline__ double warp_sumd(double v) {
    #pragma unroll
    for (int o = 16; o; o >>= 1) v += __shfl_down_sync(0xffffffffu, v, o);
    return v;
}
__device__ __forceinline__ float fsig(float x) {     // MUFU-based sigmoid
    return __fdividef(1.0f, 1.0f + __expf(-x));
}

__global__ void __launch_bounds__(256, 2)
yolo_fused(const float* __restrict__ inp, const float* __restrict__ tgt,
           const int* __restrict__ lptr, float* __restrict__ out)
{
    __shared__ float4 s_mm[NT];          // minx, maxx, miny, maxy
    __shared__ float  s_area[NT];
    __shared__ int    s_tcell[NT];       // flat cell id or -1
    __shared__ float  s_cx[NT], s_cy[NT], s_w[NT], s_h[NT];
    __shared__ int    s_cls[NT];
    __shared__ float  s_aw[3], s_ah[3];
    __shared__ int    s_l;
    __shared__ double s_acc[5];
    __shared__ int    s_islast;

    const int b   = blockIdx.y;
    const int tid = threadIdx.x;

    if (tid == 0) s_l = lptr[0];
    if (tid < 5)  s_acc[tid] = 0.0;
    __syncthreads();
    const int m0 = 6 - 3 * s_l;

    if (tid < 3) {
        s_aw[tid] = c_anchors[2 * (m0 + tid)]     * 0.125f;   // stride = 608/76 = 8
        s_ah[tid] = c_anchors[2 * (m0 + tid) + 1] * 0.125f;
    }
    if (tid < NT) {
        const float* tp = tgt + ((size_t)b * NT + tid) * 5;
        float gx = tp[0] * (float)IN_W;
        float gy = tp[1] * (float)IN_H;
        float gw = tp[2] * (float)IN_W;
        float gh = tp[3] * (float)IN_H;
        float best = -1.0f; int bn = 0;
        #pragma unroll
        for (int a = 0; a < 9; a++) {
            float aw = c_anchors[2*a] * 0.125f, ah = c_anchors[2*a+1] * 0.125f;
            float inter = fminf(gw, aw) * fminf(gh, ah);
            float r = inter / (gw * gh + aw * ah - inter);
            if (r > best) { best = r; bn = a; }
        }
        int k = bn - m0;
        int gi = (int)floorf(gx); gi = min(max(gi, 0), IN_W - 1);
        int gj = (int)floorf(gy); gj = min(max(gj, 0), IN_H - 1);
        s_tcell[tid] = (k >= 0 && k < 3) ? (k * HW + gj * IN_W + gi) : -1;
        s_mm[tid] = make_float4(gx - gw * 0.5f, gx + gw * 0.5f,
                                gy - gh * 0.5f, gy + gh * 0.5f);
        s_area[tid] = gw * gh;
        s_cx[tid] = gx; s_cy[tid] = gy; s_w[tid] = gw; s_h[tid] = gh;
        s_cls[tid] = (int)tp[4];
    }
    __syncthreads();

    const int m4 = (blockIdx.x * blockDim.x + tid) * 4;   // first cell of quad
    float objf = 0.f, loc = 0.f, clsl = 0.f, confn = 0.f, cmask = 0.f;

    if (m4 < 3 * HW) {
        const int k   = m4 / HW;                // same k for all 4 cells
        const int rem = m4 - k * HW;
        const int j   = rem / IN_W;             // same j for all 4 cells
        const int i0  = rem - j * IN_W;         // i0 % 4 == 0, i0+3 <= 75

        const size_t eoff = ((size_t)b * 255 + (size_t)k * 85) * HW + rem;
        const float4 xv = *(const float4*)(inp + eoff + 0 * HW);
        const float4 yv = *(const float4*)(inp + eoff + 1 * HW);
        const float4 wv = *(const float4*)(inp + eoff + 2 * HW);
        const float4 hv = *(const float4*)(inp + eoff + 3 * HW);
        const float4 cv = *(const float4*)(inp + eoff + 4 * HW);

        const float xr[4] = {xv.x, xv.y, xv.z, xv.w};
        const float yr[4] = {yv.x, yv.y, yv.z, yv.w};
        const float wr[4] = {wv.x, wv.y, wv.z, wv.w};
        const float hr[4] = {hv.x, hv.y, hv.z, hv.w};
        const float cr[4] = {cv.x, cv.y, cv.z, cv.w};

        const float aw = s_aw[k], ah = s_ah[k];
        float px[4], py[4], pw[4], ph[4];
        float pnx[4], pxx[4], pny[4], pxy[4], pa[4];
        #pragma unroll
        for (int c = 0; c < 4; c++) {
            px[c] = (float)(i0 + c) + fsig(xr[c]);
            py[c] = (float)j        + fsig(yr[c]);
            pw[c] = __expf(wr[c]) * aw;
            ph[c] = __expf(hr[c]) * ah;
            pnx[c] = px[c] - pw[c] * 0.5f;  pxx[c] = px[c] + pw[c] * 0.5f;
            pny[c] = py[c] - ph[c] * 0.5f;  pxy[c] = py[c] + ph[c] * 0.5f;
            pa[c]  = pw[c] * ph[c];
        }

        float ign[4] = {-1.f, -1.f, -1.f, -1.f};   // >0 => some iou > 0.5
        int   tm[4]  = {-1, -1, -1, -1};
        #pragma unroll
        for (int t = 0; t < NT; t++) {
            const float4 mm = s_mm[t];
            const float  ar = s_area[t];
            const int    tc = s_tcell[t];
            #pragma unroll
            for (int c = 0; c < 4; c++) {
                float iw = fminf(mm.y, pxx[c]) - fmaxf(mm.x, pnx[c]);
                float ih = fminf(mm.w, pxy[c]) - fmaxf(mm.z, pny[c]);
                float inter = fmaxf(iw, 0.f) * fmaxf(ih, 0.f);
                // iou > 0.5  <=>  3*inter > ar + pa
                ign[c] = fmaxf(ign[c], fmaf(3.0f, inter, -(ar + pa[c])));
                if (tc == m4 + c) tm[c] = t;
            }
        }

        #pragma unroll
        for (int c = 0; c < 4; c++) {
            const bool isobj = (tm[c] >= 0);
            const float obj = isobj ? 1.0f : 0.0f;
            objf += obj;

            float p = fsig(cr[c]);
            p = fminf(fmaxf(p, CEPS), 1.0f - CEPS);
            float arg = isobj ? p : (1.0f - p);
            float cm  = (isobj || ign[c] <= 0.0f) ? 1.0f : 0.0f;
            confn += cm * (-__logf(arg));
            cmask += cm;

            if (isobj) {
                const int t = tm[c];
                float gx = s_cx[t], gy = s_cy[t], gw = s_w[t], gh = s_h[t];
                float g_minx = gx - gw*0.5f, g_maxx = gx + gw*0.5f;
                float g_miny = gy - gh*0.5f, g_maxy = gy + gh*0.5f;
                float iw = fmaxf(fminf(g_maxx, pxx[c]) - fmaxf(g_minx, pnx[c]), 0.f);
                float ih = fmaxf(fminf(g_maxy, pxy[c]) - fmaxf(g_miny, pny[c]), 0.f);
                float inter = iw * ih;
                float uni   = fmaxf(pa[c] + gw * gh - inter, 1e-6f);
                float iou   = inter / uni;
                float dx = px[c] - gx, dy = py[c] - gy;
                float cd = dx * dx + dy * dy;
                float ew = fmaxf(fmaxf(g_maxx, pxx[c]) - fminf(g_minx, pnx[c]), 0.f);
                float eh = fmaxf(fmaxf(g_maxy, pxy[c]) - fminf(g_miny, pny[c]), 0.f);
                float ed = fmaxf(ew * ew + eh * eh, 1e-6f);
                float da = atanf(pw[c] / fmaxf(ph[c], 1e-6f))
                         - atanf(gw / fmaxf(gh, 1e-6f));
                float v  = 0.405284734569351f * da * da;  // 4/pi^2
                float alpha = v / fmaxf(1.0f - iou + v, 1e-6f);
                loc += 1.0f - (iou - cd / ed - alpha * v);

                const int cc = s_cls[t];
                const float* cbase = inp + eoff + c;
                float cs = 0.0f;
                #pragma unroll 8
                for (int ch = 0; ch < NCLS; ch++) {
                    float pc = fsig(cbase[(size_t)(5 + ch) * HW]);
                    pc = fminf(fmaxf(pc, CEPS), 1.0f - CEPS);
                    cs += (ch == cc) ? -logf(pc) : -logf(1.0f - pc);
                }
                clsl += cs;
            }
        }
    }

    // block reduction
    float vals[5] = {objf, loc, clsl, confn, cmask};
    const int lane = tid & 31;
    #pragma unroll
    for (int q = 0; q < 5; q++) {
        float v = warp_sum(vals[q]);
        if (lane == 0 && v != 0.0f) atomicAdd(&s_acc[q], (double)v);
    }
    __syncthreads();

    const int nblocks = gridDim.x * gridDim.y;
    const int bid = blockIdx.y * gridDim.x + blockIdx.x;
    if (tid < 5) g_part[bid][tid] = s_acc[tid];

    if (tid == 0) {
        __threadfence();
        unsigned v = atomicAdd(&g_count, 1u);
        s_islast = (v == (unsigned)(nblocks - 1));
        if (s_islast) g_count = 0;    // self-reset -> graph-replay deterministic
    }
    __syncthreads();
    if (!s_islast) return;

    double acc[5] = {0, 0, 0, 0, 0};
    for (int r = tid; r < nblocks; r += blockDim.x) {
        #pragma unroll
        for (int q = 0; q < 5; q++) acc[q] += g_part[r][q];
    }
    __shared__ double s_fin[5];
    if (tid < 5) s_fin[tid] = 0.0;
    __syncthreads();
    #pragma unroll
    for (int q = 0; q < 5; q++) {
        double v = warp_sumd(acc[q]);
        if (lane == 0 && v != 0.0) atomicAdd(&s_fin[q], v);
    }
    __syncthreads();
    if (tid == 0) {
        double n_obj = s_fin[0] < 1.0 ? 1.0 : s_fin[0];
        double cms   = s_fin[4] < 1.0 ? 1.0 : s_fin[4];
        const int l = s_l;
        const double balance = (l == 0) ? 0.4 : (l == 1 ? 1.0 : 4.0);
        const double obj_ratio = 5.0 * 608.0 * 608.0 / (416.0 * 416.0);
        double loss = s_fin[1] / n_obj * 0.05
                    + s_fin[3] / cms * balance * obj_ratio
                    + s_fin[2] / (n_obj * (double)NCLS);
        out[0] = (float)loss;
    }
}

extern "C" void kernel_launch(void* const* d_in, const int* in_sizes, int n_in,
                              void* d_out, int out_size)
{
    const float* inp  = (const float*)d_in[0];
    const float* tgt  = (const float*)d_in[1];
    const int*   lptr = (const int*)d_in[2];
    float* out = (float*)d_out;

    const int bs = in_sizes[0] / (255 * HW);        // 32
    const int blocks_x = (3 * HW / 4 + 255) / 256;  // 17

    yolo_fused<<<dim3(blocks_x, bs), 256>>>(inp, tgt, lptr, out);
}

// round 4
// speedup vs baseline: 2.1963x; 1.0748x over previous
#include <cuda_runtime.h>
#include <math.h>

// YoloLoss, fixed shape: input [32,255,76,76] f32, targets [32,20,5] f32, l int32.
// R4: occupancy 4 blocks/SM (regs<=64), shared byte-map for cell->target match
// (no integer ops in hot loop), division/add-free ignore test via
// ignmax = max_t(3*inter - area_t) compared once to pa. 4 cells/thread, float4 loads.

#define IN_H 76
#define IN_W 76
#define HW   (IN_H * IN_W)        // 5776
#define NT   20
#define NCLS 80
#define CEPS 1e-7f
#define MAXB 1024

// per-block partials: 0=n_obj, 1=loc_sum, 2=cls_sum, 3=conf_num, 4=conf_mask_sum
__device__ double g_part[MAXB][5];
__device__ unsigned g_count = 0;

__constant__ float c_anchors[18] = {12,16, 19,36, 40,28, 36,75, 76,55,
                                    72,146, 142,110, 192,243, 459,401};

__device__ __forceinline__ float warp_sum(float v) {
    #pragma unroll
    for (int o = 16; o; o >>= 1) v += __shfl_down_sync(0xffffffffu, v, o);
    return v;
}
__device__ __forceinline__ double warp_sumd(double v) {
    #pragma unroll
    for (int o = 16; o; o >>= 1) v += __shfl_down_sync(0xffffffffu, v, o);
    return v;
}
__device__ __forceinline__ float fsig(float x) {
    return __fdividef(1.0f, 1.0f + __expf(-x));
}

__global__ void __launch_bounds__(256, 4)
yolo_fused(const float* __restrict__ inp, const float* __restrict__ tgt,
           const int* __restrict__ lptr, float* __restrict__ out)
{
    __shared__ float4   s_mm[NT];        // minx, maxx, miny, maxy
    __shared__ float    s_area[NT];
    __shared__ int      s_tcell[NT];     // flat cell id or -1
    __shared__ float    s_cx[NT], s_cy[NT], s_w[NT], s_h[NT];
    __shared__ int      s_cls[NT];
    __shared__ unsigned s_map32[256];    // 1024 bytes: cell->target id (0xFF = none)
    __shared__ float    s_aw[3], s_ah[3];
    __shared__ int      s_l;
    __shared__ double   s_acc[5];
    __shared__ int      s_islast;

    const int b    = blockIdx.y;
    const int tid  = threadIdx.x;
    const int base = blockIdx.x * 1024;          // first cell of this block

    if (tid == 0) s_l = lptr[0];
    if (tid < 5)  s_acc[tid] = 0.0;
    s_map32[tid] = 0xFFFFFFFFu;
    __syncthreads();
    const int m0 = 6 - 3 * s_l;

    if (tid < 3) {
        s_aw[tid] = c_anchors[2 * (m0 + tid)]     * 0.125f;   // stride = 608/76 = 8
        s_ah[tid] = c_anchors[2 * (m0 + tid) + 1] * 0.125f;
    }
    if (tid < NT) {
        const float* tp = tgt + ((size_t)b * NT + tid) * 5;
        float gx = tp[0] * (float)IN_W;
        float gy = tp[1] * (float)IN_H;
        float gw = tp[2] * (float)IN_W;
        float gh = tp[3] * (float)IN_H;
        float best = -1.0f; int bn = 0;
        #pragma unroll
        for (int a = 0; a < 9; a++) {
            float aw = c_anchors[2*a] * 0.125f, ah = c_anchors[2*a+1] * 0.125f;
            float inter = fminf(gw, aw) * fminf(gh, ah);
            float r = inter / (gw * gh + aw * ah - inter);
            if (r > best) { best = r; bn = a; }
        }
        int k = bn - m0;
        int gi = (int)floorf(gx); gi = min(max(gi, 0), IN_W - 1);
        int gj = (int)floorf(gy); gj = min(max(gj, 0), IN_H - 1);
        s_tcell[tid] = (k >= 0 && k < 3) ? (k * HW + gj * IN_W + gi) : -1;
        s_mm[tid] = make_float4(gx - gw * 0.5f, gx + gw * 0.5f,
                                gy - gh * 0.5f, gy + gh * 0.5f);
        s_area[tid] = gw * gh;
        s_cx[tid] = gx; s_cy[tid] = gy; s_w[tid] = gw; s_h[tid] = gh;
        s_cls[tid] = (int)tp[4];
    }
    __syncthreads();

    // build cell->target byte map (last-write-wins = reference scatter semantics)
    if (tid == 0) {
        unsigned char* mp = (unsigned char*)s_map32;
        #pragma unroll
        for (int t = 0; t < NT; t++) {
            int d = s_tcell[t] - base;
            if ((unsigned)d < 1024u) mp[d] = (unsigned char)t;
        }
    }
    __syncthreads();

    const int m4 = base + tid * 4;               // first cell of quad
    float objf = 0.f, loc = 0.f, clsl = 0.f, confn = 0.f, cmask = 0.f;

    if (m4 < 3 * HW) {
        const int k   = m4 / HW;                 // constant across quad
        const int rem = m4 - k * HW;
        const int j   = rem / IN_W;
        const int i0  = rem - j * IN_W;

        const size_t eoff = ((size_t)b * 255 + (size_t)k * 85) * HW + rem;
        const float4 xv = *(const float4*)(inp + eoff + 0 * HW);
        const float4 yv = *(const float4*)(inp + eoff + 1 * HW);
        const float4 wv = *(const float4*)(inp + eoff + 2 * HW);
        const float4 hv = *(const float4*)(inp + eoff + 3 * HW);
        const float4 cv = *(const float4*)(inp + eoff + 4 * HW);

        const float xr[4] = {xv.x, xv.y, xv.z, xv.w};
        const float yr[4] = {yv.x, yv.y, yv.z, yv.w};
        const float wr[4] = {wv.x, wv.y, wv.z, wv.w};
        const float hr[4] = {hv.x, hv.y, hv.z, hv.w};
        const float cr[4] = {cv.x, cv.y, cv.z, cv.w};

        const float aw = s_aw[k], ah = s_ah[k];
        float pnx[4], pxx[4], pny[4], pxy[4], pa[4];
        #pragma unroll
        for (int c = 0; c < 4; c++) {
            float px = (float)(i0 + c) + fsig(xr[c]);
            float py = (float)j        + fsig(yr[c]);
            float pw = __expf(wr[c]) * aw;
            float ph = __expf(hr[c]) * ah;
            pnx[c] = px - pw * 0.5f;  pxx[c] = px + pw * 0.5f;
            pny[c] = py - ph * 0.5f;  pxy[c] = py + ph * 0.5f;
            pa[c]  = pw * ph;
        }

        // hot loop: ignmax[c] = max_t (3*inter - area_t);  iou>0.5 <=> ignmax > pa
        float ignmax[4] = {-1e30f, -1e30f, -1e30f, -1e30f};
        #pragma unroll
        for (int t = 0; t < NT; t++) {
            const float4 mm = s_mm[t];
            const float  ar = s_area[t];
            #pragma unroll
            for (int c = 0; c < 4; c++) {
                float iw = fminf(mm.y, pxx[c]) - fmaxf(mm.x, pnx[c]);
                float ih = fminf(mm.w, pxy[c]) - fmaxf(mm.z, pny[c]);
                float inter = fmaxf(iw, 0.f) * fmaxf(ih, 0.f);
                ignmax[c] = fmaxf(ignmax[c], fmaf(3.0f, inter, -ar));
            }
        }

        const unsigned mword = s_map32[tid];     // 4 match bytes for the quad

        #pragma unroll
        for (int c = 0; c < 4; c++) {
            const int t = (int)((mword >> (8 * c)) & 0xFFu);
            const bool isobj = (t != 0xFF);
            objf += isobj ? 1.0f : 0.0f;

            float p = fsig(cr[c]);
            p = fminf(fmaxf(p, CEPS), 1.0f - CEPS);
            float arg = isobj ? p : (1.0f - p);
            float cm  = (isobj || ignmax[c] <= pa[c]) ? 1.0f : 0.0f;
            confn += cm * (-__logf(arg));
            cmask += cm;

            if (isobj) {
                // recompute center/size from corners (1-ulp noise, rare path)
                float pw = pxx[c] - pnx[c];
                float ph = pxy[c] - pny[c];
                float px = 0.5f * (pnx[c] + pxx[c]);
                float py = 0.5f * (pny[c] + pxy[c]);
                float gx = s_cx[t], gy = s_cy[t], gw = s_w[t], gh = s_h[t];
                float g_minx = gx - gw*0.5f, g_maxx = gx + gw*0.5f;
                float g_miny = gy - gh*0.5f, g_maxy = gy + gh*0.5f;
                float iw = fmaxf(fminf(g_maxx, pxx[c]) - fmaxf(g_minx, pnx[c]), 0.f);
                float ih = fmaxf(fminf(g_maxy, pxy[c]) - fmaxf(g_miny, pny[c]), 0.f);
                float inter = iw * ih;
                float uni   = fmaxf(pa[c] + gw * gh - inter, 1e-6f);
                float iou   = inter / uni;
                float dx = px - gx, dy = py - gy;
                float cd = dx * dx + dy * dy;
                float ew = fmaxf(fmaxf(g_maxx, pxx[c]) - fminf(g_minx, pnx[c]), 0.f);
                float eh = fmaxf(fmaxf(g_maxy, pxy[c]) - fminf(g_miny, pny[c]), 0.f);
                float ed = fmaxf(ew * ew + eh * eh, 1e-6f);
                float da = atanf(pw / fmaxf(ph, 1e-6f))
                         - atanf(gw / fmaxf(gh, 1e-6f));
                float v  = 0.405284734569351f * da * da;  // 4/pi^2
                float alpha = v / fmaxf(1.0f - iou + v, 1e-6f);
                loc += 1.0f - (iou - cd / ed - alpha * v);

                const int cc = s_cls[t];
                const float* cbase = inp + eoff + c;
                float cs = 0.0f;
                #pragma unroll 8
                for (int ch = 0; ch < NCLS; ch++) {
                    float pc = fsig(cbase[(size_t)(5 + ch) * HW]);
                    pc = fminf(fmaxf(pc, CEPS), 1.0f - CEPS);
                    cs += (ch == cc) ? -logf(pc) : -logf(1.0f - pc);
                }
                clsl += cs;
            }
        }
    }

    // block reduction
    float vals[5] = {objf, loc, clsl, confn, cmask};
    const int lane = tid & 31;
    #pragma unroll
    for (int q = 0; q < 5; q++) {
        float v = warp_sum(vals[q]);
        if (lane == 0 && v != 0.0f) atomicAdd(&s_acc[q], (double)v);
    }
    __syncthreads();

    const int nblocks = gridDim.x * gridDim.y;
    const int bid = blockIdx.y * gridDim.x + blockIdx.x;
    if (tid < 5) g_part[bid][tid] = s_acc[tid];

    if (tid == 0) {
        __threadfence();
        unsigned v = atomicAdd(&g_count, 1u);
        s_islast = (v == (unsigned)(nblocks - 1));
        if (s_islast) g_count = 0;    // self-reset -> graph-replay deterministic
    }
    __syncthreads();
    if (!s_islast) return;

    double acc[5] = {0, 0, 0, 0, 0};
    for (int r = tid; r < nblocks; r += blockDim.x) {
        #pragma unroll
        for (int q = 0; q < 5; q++) acc[q] += g_part[r][q];
    }
    __shared__ double s_fin[5];
    if (tid < 5) s_fin[tid] = 0.0;
    __syncthreads();
    #pragma unroll
    for (int q = 0; q < 5; q++) {
        double v = warp_sumd(acc[q]);
        if (lane == 0 && v != 0.0) atomicAdd(&s_fin[q], v);
    }
    __syncthreads();
    if (tid == 0) {
        double n_obj = s_fin[0] < 1.0 ? 1.0 : s_fin[0];
        double cms   = s_fin[4] < 1.0 ? 1.0 : s_fin[4];
        const int l = s_l;
        const double balance = (l == 0) ? 0.4 : (l == 1 ? 1.0 : 4.0);
        const double obj_ratio = 5.0 * 608.0 * 608.0 / (416.0 * 416.0);
        double loss = s_fin[1] / n_obj * 0.05
                    + s_fin[3] / cms * balance * obj_ratio
                    + s_fin[2] / (n_obj * (double)NCLS);
        out[0] = (float)loss;
    }
}

extern "C" void kernel_launch(void* const* d_in, const int* in_sizes, int n_in,
                              void* d_out, int out_size)
{
    const float* inp  = (const float*)d_in[0];
    const float* tgt  = (const float*)d_in[1];
    const int*   lptr = (const int*)d_in[2];
    float* out = (float*)d_out;

    const int bs = in_sizes[0] / (255 * HW);        // 32
    const int blocks_x = (3 * HW / 4 + 255) / 256;  // 17

    yolo_fused<<<dim3(blocks_x, bs), 256>>>(inp, tgt, lptr, out);
}

// round 5
// speedup vs baseline: 2.3471x; 1.0687x over previous
#include <cuda_runtime.h>
#include <math.h>

// YoloLoss, fixed shape: input [32,255,76,76] f32, targets [32,20,5] f32, l int32.
// R5: softplus-form BCE (no clamps/selects; exact vs clipped ref for |logit|<16),
// tanh.approx sigmoid, fast-math class loop (kills divergent warp tails),
// 128-thread blocks for load balance. 4 cells/thread, float4 loads.

#define IN_H 76
#define IN_W 76
#define HW   (IN_H * IN_W)        // 5776
#define NT   20
#define NCLS 80
#define MAXB 2048

// per-block partials: 0=n_obj, 1=loc_sum, 2=cls_sum, 3=conf_num, 4=conf_mask_sum
__device__ double g_part[MAXB][5];
__device__ unsigned g_count = 0;

__constant__ float c_anchors[18] = {12,16, 19,36, 40,28, 36,75, 76,55,
                                    72,146, 142,110, 192,243, 459,401};

__device__ __forceinline__ float warp_sum(float v) {
    #pragma unroll
    for (int o = 16; o; o >>= 1) v += __shfl_down_sync(0xffffffffu, v, o);
    return v;
}
__device__ __forceinline__ double warp_sumd(double v) {
    #pragma unroll
    for (int o = 16; o; o >>= 1) v += __shfl_down_sync(0xffffffffu, v, o);
    return v;
}
__device__ __forceinline__ float ftanh(float x) {
    float r;
    asm("tanh.approx.f32 %0, %1;" : "=f"(r) : "f"(x));
    return r;
}
// sigmoid = 0.5*tanh(x/2)+0.5  (1 MUFU)
__device__ __forceinline__ float fsig(float x) {
    return fmaf(0.5f, ftanh(0.5f * x), 0.5f);
}
// softplus(z) = log(1+exp(z)) = -log(sigmoid(-z)); equals clipped-BCE term
// exactly for |z| < ~16 (clip at 1e-7 never binds for these inputs).
__device__ __forceinline__ float fsoftplus(float z) {
    return __logf(1.0f + __expf(z));
}

__global__ void __launch_bounds__(128, 8)
yolo_fused(const float* __restrict__ inp, const float* __restrict__ tgt,
           const int* __restrict__ lptr, float* __restrict__ out)
{
    __shared__ float4   s_mm[NT];        // minx, maxx, miny, maxy
    __shared__ float    s_area[NT];
    __shared__ int      s_tcell[NT];     // flat cell id or -1
    __shared__ float    s_cx[NT], s_cy[NT], s_w[NT], s_h[NT];
    __shared__ int      s_cls[NT];
    __shared__ unsigned s_map32[128];    // 512 bytes: cell->target id (0xFF = none)
    __shared__ float    s_aw[3], s_ah[3];
    __shared__ int      s_l;
    __shared__ double   s_acc[5];
    __shared__ int      s_islast;

    const int b    = blockIdx.y;
    const int tid  = threadIdx.x;
    const int base = blockIdx.x * 512;           // first cell of this block

    if (tid == 0) s_l = lptr[0];
    if (tid < 5)  s_acc[tid] = 0.0;
    s_map32[tid] = 0xFFFFFFFFu;
    __syncthreads();
    const int m0 = 6 - 3 * s_l;

    if (tid < 3) {
        s_aw[tid] = c_anchors[2 * (m0 + tid)]     * 0.125f;   // stride = 608/76 = 8
        s_ah[tid] = c_anchors[2 * (m0 + tid) + 1] * 0.125f;
    }
    if (tid < NT) {
        const float* tp = tgt + ((size_t)b * NT + tid) * 5;
        float gx = tp[0] * (float)IN_W;
        float gy = tp[1] * (float)IN_H;
        float gw = tp[2] * (float)IN_W;
        float gh = tp[3] * (float)IN_H;
        float best = -1.0f; int bn = 0;
        #pragma unroll
        for (int a = 0; a < 9; a++) {
            float aw = c_anchors[2*a] * 0.125f, ah = c_anchors[2*a+1] * 0.125f;
            float inter = fminf(gw, aw) * fminf(gh, ah);
            float r = inter / (gw * gh + aw * ah - inter);
            if (r > best) { best = r; bn = a; }
        }
        int k = bn - m0;
        int gi = (int)floorf(gx); gi = min(max(gi, 0), IN_W - 1);
        int gj = (int)floorf(gy); gj = min(max(gj, 0), IN_H - 1);
        s_tcell[tid] = (k >= 0 && k < 3) ? (k * HW + gj * IN_W + gi) : -1;
        s_mm[tid] = make_float4(gx - gw * 0.5f, gx + gw * 0.5f,
                                gy - gh * 0.5f, gy + gh * 0.5f);
        s_area[tid] = gw * gh;
        s_cx[tid] = gx; s_cy[tid] = gy; s_w[tid] = gw; s_h[tid] = gh;
        s_cls[tid] = (int)tp[4];
    }
    __syncthreads();

    // cell->target byte map (last-write-wins = reference scatter semantics)
    if (tid == 0) {
        unsigned char* mp = (unsigned char*)s_map32;
        #pragma unroll
        for (int t = 0; t < NT; t++) {
            int d = s_tcell[t] - base;
            if ((unsigned)d < 512u) mp[d] = (unsigned char)t;
        }
    }
    __syncthreads();

    const int m4 = base + tid * 4;               // first cell of quad
    float objf = 0.f, loc = 0.f, clsl = 0.f, confn = 0.f, cmask = 0.f;

    if (m4 < 3 * HW) {
        const int k   = m4 / HW;                 // constant across quad
        const int rem = m4 - k * HW;
        const int j   = rem / IN_W;
        const int i0  = rem - j * IN_W;

        const size_t eoff = ((size_t)b * 255 + (size_t)k * 85) * HW + rem;
        const float4 xv = *(const float4*)(inp + eoff + 0 * HW);
        const float4 yv = *(const float4*)(inp + eoff + 1 * HW);
        const float4 wv = *(const float4*)(inp + eoff + 2 * HW);
        const float4 hv = *(const float4*)(inp + eoff + 3 * HW);
        const float4 cv = *(const float4*)(inp + eoff + 4 * HW);

        const float xr[4] = {xv.x, xv.y, xv.z, xv.w};
        const float yr[4] = {yv.x, yv.y, yv.z, yv.w};
        const float wr[4] = {wv.x, wv.y, wv.z, wv.w};
        const float hr[4] = {hv.x, hv.y, hv.z, hv.w};
        const float cr[4] = {cv.x, cv.y, cv.z, cv.w};

        const float aw = s_aw[k], ah = s_ah[k];
        float pnx[4], pxx[4], pny[4], pxy[4];
        #pragma unroll
        for (int c = 0; c < 4; c++) {
            float px = (float)(i0 + c) + fsig(xr[c]);
            float py = (float)j        + fsig(yr[c]);
            float pw = __expf(wr[c]) * aw;
            float ph = __expf(hr[c]) * ah;
            pnx[c] = px - pw * 0.5f;  pxx[c] = px + pw * 0.5f;
            pny[c] = py - ph * 0.5f;  pxy[c] = py + ph * 0.5f;
        }

        // hot loop: ignmax[c] = max_t (3*inter - area_t);  iou>0.5 <=> ignmax > pa
        float ignmax[4] = {-1e30f, -1e30f, -1e30f, -1e30f};
        #pragma unroll
        for (int t = 0; t < NT; t++) {
            const float4 mm = s_mm[t];
            const float  ar = s_area[t];
            #pragma unroll
            for (int c = 0; c < 4; c++) {
                float iw = fminf(mm.y, pxx[c]) - fmaxf(mm.x, pnx[c]);
                float ih = fminf(mm.w, pxy[c]) - fmaxf(mm.z, pny[c]);
                float inter = fmaxf(iw, 0.f) * fmaxf(ih, 0.f);
                ignmax[c] = fmaxf(ignmax[c], fmaf(3.0f, inter, -ar));
            }
        }

        const unsigned mword = s_map32[tid];     // 4 match bytes for the quad

        #pragma unroll
        for (int c = 0; c < 4; c++) {
            const int t = (int)((mword >> (8 * c)) & 0xFFu);
            const bool isobj = (t != 0xFF);
            const float pa = (pxx[c] - pnx[c]) * (pxy[c] - pny[c]);
            objf += isobj ? 1.0f : 0.0f;

            // conf BCE: -log(sig(cr)) = softplus(-cr); -log(1-sig(cr)) = softplus(cr)
            float cm  = (isobj || ignmax[c] <= pa) ? 1.0f : 0.0f;
            confn += cm * fsoftplus(isobj ? -cr[c] : cr[c]);
            cmask += cm;

            if (isobj) {
                float pw = pxx[c] - pnx[c];
                float ph = pxy[c] - pny[c];
                float px = 0.5f * (pnx[c] + pxx[c]);
                float py = 0.5f * (pny[c] + pxy[c]);
                float gx = s_cx[t], gy = s_cy[t], gw = s_w[t], gh = s_h[t];
                float g_minx = gx - gw*0.5f, g_maxx = gx + gw*0.5f;
                float g_miny = gy - gh*0.5f, g_maxy = gy + gh*0.5f;
                float iw = fmaxf(fminf(g_maxx, pxx[c]) - fmaxf(g_minx, pnx[c]), 0.f);
                float ih = fmaxf(fminf(g_maxy, pxy[c]) - fmaxf(g_miny, pny[c]), 0.f);
                float inter = iw * ih;
                float uni   = fmaxf(pa + gw * gh - inter, 1e-6f);
                float iou   = inter / uni;
                float dx = px - gx, dy = py - gy;
                float cd = dx * dx + dy * dy;
                float ew = fmaxf(fmaxf(g_maxx, pxx[c]) - fminf(g_minx, pnx[c]), 0.f);
                float eh = fmaxf(fmaxf(g_maxy, pxy[c]) - fminf(g_miny, pny[c]), 0.f);
                float ed = fmaxf(ew * ew + eh * eh, 1e-6f);
                float da = atanf(pw / fmaxf(ph, 1e-6f))
                         - atanf(gw / fmaxf(gh, 1e-6f));
                float v  = 0.405284734569351f * da * da;  // 4/pi^2
                float alpha = v / fmaxf(1.0f - iou + v, 1e-6f);
                loc += 1.0f - (iou - cd / ed - alpha * v);

                // class BCE: softplus form, fast math (terms O(0.7), rel err ~1e-6)
                const int cc = s_cls[t];
                const float* cbase = inp + eoff + c;
                float cs = 0.0f;
                #pragma unroll 8
                for (int ch = 0; ch < NCLS; ch++) {
                    float z = cbase[(size_t)(5 + ch) * HW];
                    cs += fsoftplus((ch == cc) ? -z : z);
                }
                clsl += cs;
            }
        }
    }

    // block reduction
    float vals[5] = {objf, loc, clsl, confn, cmask};
    const int lane = tid & 31;
    #pragma unroll
    for (int q = 0; q < 5; q++) {
        float v = warp_sum(vals[q]);
        if (lane == 0 && v != 0.0f) atomicAdd(&s_acc[q], (double)v);
    }
    __syncthreads();

    const int nblocks = gridDim.x * gridDim.y;
    const int bid = blockIdx.y * gridDim.x + blockIdx.x;
    if (tid < 5) g_part[bid][tid] = s_acc[tid];

    if (tid == 0) {
        __threadfence();
        unsigned v = atomicAdd(&g_count, 1u);
        s_islast = (v == (unsigned)(nblocks - 1));
        if (s_islast) g_count = 0;    // self-reset -> graph-replay deterministic
    }
    __syncthreads();
    if (!s_islast) return;

    double acc[5] = {0, 0, 0, 0, 0};
    for (int r = tid; r < nblocks; r += blockDim.x) {
        #pragma unroll
        for (int q = 0; q < 5; q++) acc[q] += g_part[r][q];
    }
    __shared__ double s_fin[5];
    if (tid < 5) s_fin[tid] = 0.0;
    __syncthreads();
    #pragma unroll
    for (int q = 0; q < 5; q++) {
        double v = warp_sumd(acc[q]);
        if (lane == 0 && v != 0.0) atomicAdd(&s_fin[q], v);
    }
    __syncthreads();
    if (tid == 0) {
        double n_obj = s_fin[0] < 1.0 ? 1.0 : s_fin[0];
        double cms   = s_fin[4] < 1.0 ? 1.0 : s_fin[4];
        const int l = s_l;
        const double balance = (l == 0) ? 0.4 : (l == 1 ? 1.0 : 4.0);
        const double obj_ratio = 5.0 * 608.0 * 608.0 / (416.0 * 416.0);
        double loss = s_fin[1] / n_obj * 0.05
                    + s_fin[3] / cms * balance * obj_ratio
                    + s_fin[2] / (n_obj * (double)NCLS);
        out[0] = (float)loss;
    }
}

extern "C" void kernel_launch(void* const* d_in, const int* in_sizes, int n_in,
                              void* d_out, int out_size)
{
    const float* inp  = (const float*)d_in[0];
    const float* tgt  = (const float*)d_in[1];
    const int*   lptr = (const int*)d_in[2];
    float* out = (float*)d_out;

    const int bs = in_sizes[0] / (255 * HW);        // 32
    const int blocks_x = (3 * HW / 4 + 127) / 128;  // 34

    yolo_fused<<<dim3(blocks_x, bs), 128>>>(inp, tgt, lptr, out);
}

// round 6
// speedup vs baseline: 2.5824x; 1.1003x over previous
#include <cuda_runtime.h>
#include <math.h>

// YoloLoss, fixed shape: input [32,255,76,76] f32, targets [32,20,5] f32, l int32.
// R6: per-block target pruning for the ignore loop. Trigger 3*inter-ar > pa requires
// ar/2 < pa < 2*ar and y-overlap with the block's cells; block-reduce pa/pny/pxy
// bounds, ballot-compact surviving targets (typically ~1 of 20), run the ignore loop
// only over survivors. Match path (byte map) unchanged. 4 cells/thread, float4 loads.

#define IN_H 76
#define IN_W 76
#define HW   (IN_H * IN_W)        // 5776
#define NT   20
#define NCLS 80
#define MAXB 2048

// per-block partials: 0=n_obj, 1=loc_sum, 2=cls_sum, 3=conf_num, 4=conf_mask_sum
__device__ double g_part[MAXB][5];
__device__ unsigned g_count = 0;

__constant__ float c_anchors[18] = {12,16, 19,36, 40,28, 36,75, 76,55,
                                    72,146, 142,110, 192,243, 459,401};

__device__ __forceinline__ float warp_sum(float v) {
    #pragma unroll
    for (int o = 16; o; o >>= 1) v += __shfl_down_sync(0xffffffffu, v, o);
    return v;
}
__device__ __forceinline__ float warp_min(float v) {
    #pragma unroll
    for (int o = 16; o; o >>= 1) v = fminf(v, __shfl_down_sync(0xffffffffu, v, o));
    return v;
}
__device__ __forceinline__ float warp_max(float v) {
    #pragma unroll
    for (int o = 16; o; o >>= 1) v = fmaxf(v, __shfl_down_sync(0xffffffffu, v, o));
    return v;
}
__device__ __forceinline__ double warp_sumd(double v) {
    #pragma unroll
    for (int o = 16; o; o >>= 1) v += __shfl_down_sync(0xffffffffu, v, o);
    return v;
}
__device__ __forceinline__ float ftanh(float x) {
    float r;
    asm("tanh.approx.f32 %0, %1;" : "=f"(r) : "f"(x));
    return r;
}
__device__ __forceinline__ float fsig(float x) {      // 1 MUFU sigmoid
    return fmaf(0.5f, ftanh(0.5f * x), 0.5f);
}
// softplus(z) = -log(sigmoid(-z)); equals clipped-BCE term exactly for |z| < ~16
__device__ __forceinline__ float fsoftplus(float z) {
    return __logf(1.0f + __expf(z));
}

__global__ void __launch_bounds__(128, 8)
yolo_fused(const float* __restrict__ inp, const float* __restrict__ tgt,
           const int* __restrict__ lptr, float* __restrict__ out)
{
    __shared__ float4   s_mm[NT];        // minx, maxx, miny, maxy
    __shared__ float    s_area[NT];
    __shared__ int      s_tcell[NT];     // flat cell id or -1
    __shared__ float    s_cx[NT], s_cy[NT], s_w[NT], s_h[NT];
    __shared__ int      s_cls[NT];
    __shared__ unsigned s_map32[128];    // 512 bytes: cell->target id (0xFF = none)
    __shared__ float    s_aw[3], s_ah[3];
    __shared__ int      s_l;
    __shared__ double   s_acc[5];
    __shared__ int      s_islast;
    __shared__ float    s_red[4][4];     // [quantity][warp]: pamin,pamax,pnymin,pxymax
    __shared__ int      s_list[NT];
    __shared__ int      s_cnt;

    const int b    = blockIdx.y;
    const int tid  = threadIdx.x;
    const int wid  = tid >> 5;
    const int lane = tid & 31;
    const int base = blockIdx.x * 512;           // first cell of this block

    if (tid == 0) s_l = lptr[0];
    if (tid < 5)  s_acc[tid] = 0.0;
    s_map32[tid] = 0xFFFFFFFFu;
    __syncthreads();
    const int m0 = 6 - 3 * s_l;

    if (tid < 3) {
        s_aw[tid] = c_anchors[2 * (m0 + tid)]     * 0.125f;   // stride = 608/76 = 8
        s_ah[tid] = c_anchors[2 * (m0 + tid) + 1] * 0.125f;
    }
    if (tid < NT) {
        const float* tp = tgt + ((size_t)b * NT + tid) * 5;
        float gx = tp[0] * (float)IN_W;
        float gy = tp[1] * (float)IN_H;
        float gw = tp[2] * (float)IN_W;
        float gh = tp[3] * (float)IN_H;
        float best = -1.0f; int bn = 0;
        #pragma unroll
        for (int a = 0; a < 9; a++) {
            float aw = c_anchors[2*a] * 0.125f, ah = c_anchors[2*a+1] * 0.125f;
            float inter = fminf(gw, aw) * fminf(gh, ah);
            float r = inter / (gw * gh + aw * ah - inter);
            if (r > best) { best = r; bn = a; }
        }
        int k = bn - m0;
        int gi = (int)floorf(gx); gi = min(max(gi, 0), IN_W - 1);
        int gj = (int)floorf(gy); gj = min(max(gj, 0), IN_H - 1);
        s_tcell[tid] = (k >= 0 && k < 3) ? (k * HW + gj * IN_W + gi) : -1;
        s_mm[tid] = make_float4(gx - gw * 0.5f, gx + gw * 0.5f,
                                gy - gh * 0.5f, gy + gh * 0.5f);
        s_area[tid] = gw * gh;
        s_cx[tid] = gx; s_cy[tid] = gy; s_w[tid] = gw; s_h[tid] = gh;
        s_cls[tid] = (int)tp[4];
    }
    __syncthreads();

    // cell->target byte map (last-write-wins = reference scatter semantics)
    if (tid == 0) {
        unsigned char* mp = (unsigned char*)s_map32;
        #pragma unroll
        for (int t = 0; t < NT; t++) {
            int d = s_tcell[t] - base;
            if ((unsigned)d < 512u) mp[d] = (unsigned char)t;
        }
    }

    const int m4 = base + tid * 4;               // first cell of quad
    const bool vld = (m4 < 3 * HW);

    // ---- prologue: decode 4 cells ----
    float pnx[4], pxx[4], pny[4], pxy[4], pa[4];
    float cr[4];
    size_t eoff = 0;
    if (vld) {
        const int k   = m4 / HW;                 // constant across quad
        const int rem = m4 - k * HW;
        const int j   = rem / IN_W;
        const int i0  = rem - j * IN_W;

        eoff = ((size_t)b * 255 + (size_t)k * 85) * HW + rem;
        const float4 xv = *(const float4*)(inp + eoff + 0 * HW);
        const float4 yv = *(const float4*)(inp + eoff + 1 * HW);
        const float4 wv = *(const float4*)(inp + eoff + 2 * HW);
        const float4 hv = *(const float4*)(inp + eoff + 3 * HW);
        const float4 cv = *(const float4*)(inp + eoff + 4 * HW);
        const float xr[4] = {xv.x, xv.y, xv.z, xv.w};
        const float yr[4] = {yv.x, yv.y, yv.z, yv.w};
        const float wr[4] = {wv.x, wv.y, wv.z, wv.w};
        const float hr[4] = {hv.x, hv.y, hv.z, hv.w};
        cr[0] = cv.x; cr[1] = cv.y; cr[2] = cv.z; cr[3] = cv.w;

        const float aw = s_aw[k], ah = s_ah[k];
        #pragma unroll
        for (int c = 0; c < 4; c++) {
            float px = (float)(i0 + c) + fsig(xr[c]);
            float py = (float)j        + fsig(yr[c]);
            float pw = __expf(wr[c]) * aw;
            float ph = __expf(hr[c]) * ah;
            pnx[c] = px - pw * 0.5f;  pxx[c] = px + pw * 0.5f;
            pny[c] = py - ph * 0.5f;  pxy[c] = py + ph * 0.5f;
            pa[c]  = pw * ph;
        }
    }

    // ---- block bounds for pruning ----
    float pamin = 1e30f, pamax = -1e30f, pnymin = 1e30f, pxymax = -1e30f;
    if (vld) {
        #pragma unroll
        for (int c = 0; c < 4; c++) {
            pamin  = fminf(pamin,  pa[c]);  pamax  = fmaxf(pamax,  pa[c]);
            pnymin = fminf(pnymin, pny[c]); pxymax = fmaxf(pxymax, pxy[c]);
        }
    }
    pamin = warp_min(pamin); pamax = warp_max(pamax);
    pnymin = warp_min(pnymin); pxymax = warp_max(pxymax);
    if (lane == 0) {
        s_red[0][wid] = pamin;  s_red[1][wid] = pamax;
        s_red[2][wid] = pnymin; s_red[3][wid] = pxymax;
    }
    __syncthreads();

    // ---- warp 0: prune + compact target list ----
    if (tid < 32) {
        bool keep = false;
        if (tid < NT) {
            float bpamin  = fminf(fminf(s_red[0][0], s_red[0][1]), fminf(s_red[0][2], s_red[0][3]));
            float bpamax  = fmaxf(fmaxf(s_red[1][0], s_red[1][1]), fmaxf(s_red[1][2], s_red[1][3]));
            float bpnymin = fminf(fminf(s_red[2][0], s_red[2][1]), fminf(s_red[2][2], s_red[2][3]));
            float bpxymax = fmaxf(fmaxf(s_red[3][0], s_red[3][1]), fmaxf(s_red[3][2], s_red[3][3]));
            float ar = s_area[tid];
            float4 mm = s_mm[tid];
            // trigger 3*inter-ar > pa needs ar/2 < pa < 2*ar (margined) and y-overlap
            keep = (bpamin < 2.0002f * ar) && (2.0002f * bpamax > ar)
                && (mm.w >= bpnymin) && (mm.z <= bpxymax);
        }
        unsigned msk = __ballot_sync(0xffffffffu, keep);
        if (keep) s_list[__popc(msk & ((1u << tid) - 1u))] = tid;
        if (tid == 0) s_cnt = __popc(msk);
    }
    __syncthreads();

    float objf = 0.f, loc = 0.f, clsl = 0.f, confn = 0.f, cmask = 0.f;

    if (vld) {
        // ignore loop over surviving targets only
        float ignmax[4] = {-1e30f, -1e30f, -1e30f, -1e30f};
        const int cnt = s_cnt;
        for (int tt = 0; tt < cnt; tt++) {
            const int t = s_list[tt];
            const float4 mm = s_mm[t];
            const float  ar = s_area[t];
            #pragma unroll
            for (int c = 0; c < 4; c++) {
                float iw = fminf(mm.y, pxx[c]) - fmaxf(mm.x, pnx[c]);
                float ih = fminf(mm.w, pxy[c]) - fmaxf(mm.z, pny[c]);
                float inter = fmaxf(iw, 0.f) * fmaxf(ih, 0.f);
                ignmax[c] = fmaxf(ignmax[c], fmaf(3.0f, inter, -ar));
            }
        }

        const unsigned mword = s_map32[tid];     // 4 match bytes for the quad

        #pragma unroll
        for (int c = 0; c < 4; c++) {
            const int t = (int)((mword >> (8 * c)) & 0xFFu);
            const bool isobj = (t != 0xFF);
            objf += isobj ? 1.0f : 0.0f;

            float cm = (isobj || ignmax[c] <= pa[c]) ? 1.0f : 0.0f;
            confn += cm * fsoftplus(isobj ? -cr[c] : cr[c]);
            cmask += cm;

            if (isobj) {
                float pw = pxx[c] - pnx[c];
                float ph = pxy[c] - pny[c];
                float px = 0.5f * (pnx[c] + pxx[c]);
                float py = 0.5f * (pny[c] + pxy[c]);
                float gx = s_cx[t], gy = s_cy[t], gw = s_w[t], gh = s_h[t];
                float g_minx = gx - gw*0.5f, g_maxx = gx + gw*0.5f;
                float g_miny = gy - gh*0.5f, g_maxy = gy + gh*0.5f;
                float iw = fmaxf(fminf(g_maxx, pxx[c]) - fmaxf(g_minx, pnx[c]), 0.f);
                float ih = fmaxf(fminf(g_maxy, pxy[c]) - fmaxf(g_miny, pny[c]), 0.f);
                float inter = iw * ih;
                float uni   = fmaxf(pa[c] + gw * gh - inter, 1e-6f);
                float iou   = inter / uni;
                float dx = px - gx, dy = py - gy;
                float cd = dx * dx + dy * dy;
                float ew = fmaxf(fmaxf(g_maxx, pxx[c]) - fminf(g_minx, pnx[c]), 0.f);
                float eh = fmaxf(fmaxf(g_maxy, pxy[c]) - fminf(g_miny, pny[c]), 0.f);
                float ed = fmaxf(ew * ew + eh * eh, 1e-6f);
                float da = atanf(pw / fmaxf(ph, 1e-6f))
                         - atanf(gw / fmaxf(gh, 1e-6f));
                float v  = 0.405284734569351f * da * da;  // 4/pi^2
                float alpha = v / fmaxf(1.0f - iou + v, 1e-6f);
                loc += 1.0f - (iou - cd / ed - alpha * v);

                const int cc = s_cls[t];
                const float* cbase = inp + eoff + c;
                float cs = 0.0f;
                #pragma unroll 8
                for (int ch = 0; ch < NCLS; ch++) {
                    float z = cbase[(size_t)(5 + ch) * HW];
                    cs += fsoftplus((ch == cc) ? -z : z);
                }
                clsl += cs;
            }
        }
    }

    // block reduction
    float vals[5] = {objf, loc, clsl, confn, cmask};
    #pragma unroll
    for (int q = 0; q < 5; q++) {
        float v = warp_sum(vals[q]);
        if (lane == 0 && v != 0.0f) atomicAdd(&s_acc[q], (double)v);
    }
    __syncthreads();

    const int nblocks = gridDim.x * gridDim.y;
    const int bid = blockIdx.y * gridDim.x + blockIdx.x;
    if (tid < 5) g_part[bid][tid] = s_acc[tid];

    if (tid == 0) {
        __threadfence();
        unsigned v = atomicAdd(&g_count, 1u);
        s_islast = (v == (unsigned)(nblocks - 1));
        if (s_islast) g_count = 0;    // self-reset -> graph-replay deterministic
    }
    __syncthreads();
    if (!s_islast) return;

    double acc[5] = {0, 0, 0, 0, 0};
    for (int r = tid; r < nblocks; r += blockDim.x) {
        #pragma unroll
        for (int q = 0; q < 5; q++) acc[q] += g_part[r][q];
    }
    __shared__ double s_fin[5];
    if (tid < 5) s_fin[tid] = 0.0;
    __syncthreads();
    #pragma unroll
    for (int q = 0; q < 5; q++) {
        double v = warp_sumd(acc[q]);
        if (lane == 0 && v != 0.0) atomicAdd(&s_fin[q], v);
    }
    __syncthreads();
    if (tid == 0) {
        double n_obj = s_fin[0] < 1.0 ? 1.0 : s_fin[0];
        double cms   = s_fin[4] < 1.0 ? 1.0 : s_fin[4];
        const int l = s_l;
        const double balance = (l == 0) ? 0.4 : (l == 1 ? 1.0 : 4.0);
        const double obj_ratio = 5.0 * 608.0 * 608.0 / (416.0 * 416.0);
        double loss = s_fin[1] / n_obj * 0.05
                    + s_fin[3] / cms * balance * obj_ratio
                    + s_fin[2] / (n_obj * (double)NCLS);
        out[0] = (float)loss;
    }
}

extern "C" void kernel_launch(void* const* d_in, const int* in_sizes, int n_in,
                              void* d_out, int out_size)
{
    const float* inp  = (const float*)d_in[0];
    const float* tgt  = (const float*)d_in[1];
    const int*   lptr = (const int*)d_in[2];
    float* out = (float*)d_out;

    const int bs = in_sizes[0] / (255 * HW);        // 32
    const int blocks_x = (3 * HW / 4 + 127) / 128;  // 34

    yolo_fused<<<dim3(blocks_x, bs), 128>>>(inp, tgt, lptr, out);
}

// round 7
// speedup vs baseline: 3.1757x; 1.2297x over previous
#include <cuda_runtime.h>
#include <math.h>

// YoloLoss, fixed shape: input [32,255,76,76] f32, targets [32,20,5] f32, l int32.
// R7: warp-cooperative class BCE (kills the 80-scattered-load divergent tail),
// input loads issued before target preprocessing (overlapped DRAM latencies),
// atomicMax int scatter-map (parallel build, last-write-wins == max t).
// Keeps R6 target pruning for the ignore loop. 4 cells/thread, float4 loads.

#define IN_H 76
#define IN_W 76
#define HW   (IN_H * IN_W)        // 5776
#define NT   20
#define NCLS 80
#define MAXB 2048

// per-block partials: 0=n_obj, 1=loc_sum, 2=cls_sum, 3=conf_num, 4=conf_mask_sum
__device__ double g_part[MAXB][5];
__device__ unsigned g_count = 0;

__constant__ float c_anchors[18] = {12,16, 19,36, 40,28, 36,75, 76,55,
                                    72,146, 142,110, 192,243, 459,401};

__device__ __forceinline__ float warp_sum(float v) {
    #pragma unroll
    for (int o = 16; o; o >>= 1) v += __shfl_down_sync(0xffffffffu, v, o);
    return v;
}
__device__ __forceinline__ float warp_min(float v) {
    #pragma unroll
    for (int o = 16; o; o >>= 1) v = fminf(v, __shfl_down_sync(0xffffffffu, v, o));
    return v;
}
__device__ __forceinline__ float warp_max(float v) {
    #pragma unroll
    for (int o = 16; o; o >>= 1) v = fmaxf(v, __shfl_down_sync(0xffffffffu, v, o));
    return v;
}
__device__ __forceinline__ double warp_sumd(double v) {
    #pragma unroll
    for (int o = 16; o; o >>= 1) v += __shfl_down_sync(0xffffffffu, v, o);
    return v;
}
__device__ __forceinline__ float ftanh(float x) {
    float r;
    asm("tanh.approx.f32 %0, %1;" : "=f"(r) : "f"(x));
    return r;
}
__device__ __forceinline__ float fsig(float x) {      // 1 MUFU sigmoid
    return fmaf(0.5f, ftanh(0.5f * x), 0.5f);
}
// softplus(z) = -log(sigmoid(-z)); equals clipped-BCE term exactly for |z| < ~16
__device__ __forceinline__ float fsoftplus(float z) {
    return __logf(1.0f + __expf(z));
}

__global__ void __launch_bounds__(128, 8)
yolo_fused(const float* __restrict__ inp, const float* __restrict__ tgt,
           const int* __restrict__ lptr, float* __restrict__ out)
{
    __shared__ float4   s_mm[NT];        // minx, maxx, miny, maxy
    __shared__ float    s_area[NT];
    __shared__ float    s_cx[NT], s_cy[NT], s_w[NT], s_h[NT];
    __shared__ int      s_cls[NT];
    __shared__ int      s_map[512];      // cell->target (-1 = none), atomicMax build
    __shared__ double   s_acc[5];
    __shared__ int      s_islast;
    __shared__ float    s_red[4][4];     // [quantity][warp]
    __shared__ int      s_list[NT];
    __shared__ int      s_cnt;

    const int b    = blockIdx.y;
    const int tid  = threadIdx.x;
    const int wid  = tid >> 5;
    const int lane = tid & 31;
    const int base = blockIdx.x * 512;

    const int m4  = base + tid * 4;              // first cell of quad
    const bool vld = (m4 < 3 * HW);
    const int k   = m4 / HW;                     // constant across quad
    const int rem = m4 - k * HW;
    const int j   = rem / IN_W;
    const int i0  = rem - j * IN_W;
    const size_t eoff = ((size_t)b * 255 + (size_t)k * 85) * HW + rem;

    // ---- issue input loads FIRST (overlap with target preprocessing) ----
    float4 xv, yv, wv, hv, cv;
    if (vld) {
        xv = *(const float4*)(inp + eoff + 0 * HW);
        yv = *(const float4*)(inp + eoff + 1 * HW);
        wv = *(const float4*)(inp + eoff + 2 * HW);
        hv = *(const float4*)(inp + eoff + 3 * HW);
        cv = *(const float4*)(inp + eoff + 4 * HW);
    }
    const int l  = __ldg(lptr);
    const int m0 = 6 - 3 * l;

    // map init (parallel)
    s_map[tid] = -1; s_map[tid + 128] = -1; s_map[tid + 256] = -1; s_map[tid + 384] = -1;
    if (tid < 5) s_acc[tid] = 0.0;

    // ---- target preprocessing (concurrent with in-flight input loads) ----
    if (tid < NT) {
        const float* tp = tgt + ((size_t)b * NT + tid) * 5;
        float gx = tp[0] * (float)IN_W;
        float gy = tp[1] * (float)IN_H;
        float gw = tp[2] * (float)IN_W;
        float gh = tp[3] * (float)IN_H;
        float best = -1.0f; int bn = 0;
        #pragma unroll
        for (int a = 0; a < 9; a++) {
            float aw = c_anchors[2*a] * 0.125f, ah = c_anchors[2*a+1] * 0.125f;
            float inter = fminf(gw, aw) * fminf(gh, ah);
            float r = inter / (gw * gh + aw * ah - inter);
            if (r > best) { best = r; bn = a; }
        }
        int kk = bn - m0;
        int gi = (int)floorf(gx); gi = min(max(gi, 0), IN_W - 1);
        int gj = (int)floorf(gy); gj = min(max(gj, 0), IN_H - 1);
        if (kk >= 0 && kk < 3) {
            int d = kk * HW + gj * IN_W + gi - base;
            if ((unsigned)d < 512u) atomicMax(&s_map[d], tid);  // larger t wins = ref order
        }
        s_mm[tid] = make_float4(gx - gw * 0.5f, gx + gw * 0.5f,
                                gy - gh * 0.5f, gy + gh * 0.5f);
        s_area[tid] = gw * gh;
        s_cx[tid] = gx; s_cy[tid] = gy; s_w[tid] = gw; s_h[tid] = gh;
        s_cls[tid] = (int)tp[4];
    }

    // ---- decode (independent of shared: anchors straight from constant) ----
    float pnx[4], pxx[4], pny[4], pxy[4], pa[4];
    float cr[4];
    if (vld) {
        const float aw = c_anchors[2 * (m0 + k)]     * 0.125f;
        const float ah = c_anchors[2 * (m0 + k) + 1] * 0.125f;
        const float xr[4] = {xv.x, xv.y, xv.z, xv.w};
        const float yr[4] = {yv.x, yv.y, yv.z, yv.w};
        const float wr[4] = {wv.x, wv.y, wv.z, wv.w};
        const float hr[4] = {hv.x, hv.y, hv.z, hv.w};
        cr[0] = cv.x; cr[1] = cv.y; cr[2] = cv.z; cr[3] = cv.w;
        #pragma unroll
        for (int c = 0; c < 4; c++) {
            float px = (float)(i0 + c) + fsig(xr[c]);
            float py = (float)j        + fsig(yr[c]);
            float pw = __expf(wr[c]) * aw;
            float ph = __expf(hr[c]) * ah;
            pnx[c] = px - pw * 0.5f;  pxx[c] = px + pw * 0.5f;
            pny[c] = py - ph * 0.5f;  pxy[c] = py + ph * 0.5f;
            pa[c]  = pw * ph;
        }
    }

    // ---- block bounds for pruning ----
    float pamin = 1e30f, pamax = -1e30f, pnymin = 1e30f, pxymax = -1e30f;
    if (vld) {
        #pragma unroll
        for (int c = 0; c < 4; c++) {
            pamin  = fminf(pamin,  pa[c]);  pamax  = fmaxf(pamax,  pa[c]);
            pnymin = fminf(pnymin, pny[c]); pxymax = fmaxf(pxymax, pxy[c]);
        }
    }
    pamin = warp_min(pamin); pamax = warp_max(pamax);
    pnymin = warp_min(pnymin); pxymax = warp_max(pxymax);
    if (lane == 0) {
        s_red[0][wid] = pamin;  s_red[1][wid] = pamax;
        s_red[2][wid] = pnymin; s_red[3][wid] = pxymax;
    }
    __syncthreads();   // targets, map, bounds all ready

    // ---- warp 0: prune + compact target list ----
    if (tid < 32) {
        bool keep = false;
        if (tid < NT) {
            float bpamin  = fminf(fminf(s_red[0][0], s_red[0][1]), fminf(s_red[0][2], s_red[0][3]));
            float bpamax  = fmaxf(fmaxf(s_red[1][0], s_red[1][1]), fmaxf(s_red[1][2], s_red[1][3]));
            float bpnymin = fminf(fminf(s_red[2][0], s_red[2][1]), fminf(s_red[2][2], s_red[2][3]));
            float bpxymax = fmaxf(fmaxf(s_red[3][0], s_red[3][1]), fmaxf(s_red[3][2], s_red[3][3]));
            float ar = s_area[tid];
            float4 mm = s_mm[tid];
            keep = (bpamin < 2.0002f * ar) && (2.0002f * bpamax > ar)
                && (mm.w >= bpnymin) && (mm.z <= bpxymax);
        }
        unsigned msk = __ballot_sync(0xffffffffu, keep);
        if (keep) s_list[__popc(msk & ((1u << tid) - 1u))] = tid;
        if (tid == 0) s_cnt = __popc(msk);
    }
    __syncthreads();

    float objf = 0.f, loc = 0.f, clsl = 0.f, confn = 0.f, cmask = 0.f;
    bool objc[4] = {false, false, false, false};
    int  tq[4];

    if (vld) {
        // ignore loop over surviving targets only
        float ignmax[4] = {-1e30f, -1e30f, -1e30f, -1e30f};
        const int cnt = s_cnt;
        for (int tt = 0; tt < cnt; tt++) {
            const int t = s_list[tt];
            const float4 mm = s_mm[t];
            const float  ar = s_area[t];
            #pragma unroll
            for (int c = 0; c < 4; c++) {
                float iw = fminf(mm.y, pxx[c]) - fmaxf(mm.x, pnx[c]);
                float ih = fminf(mm.w, pxy[c]) - fmaxf(mm.z, pny[c]);
                float inter = fmaxf(iw, 0.f) * fmaxf(ih, 0.f);
                ignmax[c] = fmaxf(ignmax[c], fmaf(3.0f, inter, -ar));
            }
        }

        const int4 mi = ((const int4*)s_map)[tid];
        tq[0] = mi.x; tq[1] = mi.y; tq[2] = mi.z; tq[3] = mi.w;

        #pragma unroll
        for (int c = 0; c < 4; c++) {
            const int t = tq[c];
            const bool isobj = (t >= 0);
            objc[c] = isobj;
            objf += isobj ? 1.0f : 0.0f;

            float cm = (isobj || ignmax[c] <= pa[c]) ? 1.0f : 0.0f;
            confn += cm * fsoftplus(isobj ? -cr[c] : cr[c]);
            cmask += cm;

            if (isobj) {   // rare: CIoU only (class BCE handled cooperatively below)
                float pw = pxx[c] - pnx[c];
                float ph = pxy[c] - pny[c];
                float px = 0.5f * (pnx[c] + pxx[c]);
                float py = 0.5f * (pny[c] + pxy[c]);
                float gx = s_cx[t], gy = s_cy[t], gw = s_w[t], gh = s_h[t];
                float g_minx = gx - gw*0.5f, g_maxx = gx + gw*0.5f;
                float g_miny = gy - gh*0.5f, g_maxy = gy + gh*0.5f;
                float iw = fmaxf(fminf(g_maxx, pxx[c]) - fmaxf(g_minx, pnx[c]), 0.f);
                float ih = fmaxf(fminf(g_maxy, pxy[c]) - fmaxf(g_miny, pny[c]), 0.f);
                float inter = iw * ih;
                float uni   = fmaxf(pa[c] + gw * gh - inter, 1e-6f);
                float iou   = inter / uni;
                float dx = px - gx, dy = py - gy;
                float cd = dx * dx + dy * dy;
                float ew = fmaxf(fmaxf(g_maxx, pxx[c]) - fminf(g_minx, pnx[c]), 0.f);
                float eh = fmaxf(fmaxf(g_maxy, pxy[c]) - fminf(g_miny, pny[c]), 0.f);
                float ed = fmaxf(ew * ew + eh * eh, 1e-6f);
                float da = atanf(pw / fmaxf(ph, 1e-6f))
                         - atanf(gw / fmaxf(gh, 1e-6f));
                float v  = 0.405284734569351f * da * da;  // 4/pi^2
                float alpha = v / fmaxf(1.0f - iou + v, 1e-6f);
                loc += 1.0f - (iou - cd / ed - alpha * v);
            }
        }
    }

    // ---- warp-cooperative class BCE over obj cells (all 32 lanes split 80 ch) ----
    #pragma unroll
    for (int c = 0; c < 4; c++) {
        unsigned msk = __ballot_sync(0xffffffffu, vld && objc[c]);
        while (msk) {
            const int src = __ffs(msk) - 1;
            msk &= msk - 1;
            const int cell = __shfl_sync(0xffffffffu, m4 + c, src);
            const int t    = s_map[cell - base];          // broadcast LDS
            const int cc   = s_cls[t];
            const int k2   = cell / HW;
            const int rem2 = cell - k2 * HW;
            const size_t off = ((size_t)b * 255 + (size_t)k2 * 85) * HW + rem2;
            float cs = 0.0f;
            #pragma unroll
            for (int q = 0; q < 3; q++) {
                int ch = lane + q * 32;
                if (ch < NCLS) {
                    float z = inp[off + (size_t)(5 + ch) * HW];
                    cs += fsoftplus((ch == cc) ? -z : z);
                }
            }
            cs = warp_sum(cs);
            if (lane == 0) clsl += cs;
        }
    }

    // block reduction
    float vals[5] = {objf, loc, clsl, confn, cmask};
    #pragma unroll
    for (int q = 0; q < 5; q++) {
        float v = warp_sum(vals[q]);
        if (lane == 0 && v != 0.0f) atomicAdd(&s_acc[q], (double)v);
    }
    __syncthreads();

    const int nblocks = gridDim.x * gridDim.y;
    const int bid = blockIdx.y * gridDim.x + blockIdx.x;
    if (tid < 5) g_part[bid][tid] = s_acc[tid];

    if (tid == 0) {
        __threadfence();
        unsigned v = atomicAdd(&g_count, 1u);
        s_islast = (v == (unsigned)(nblocks - 1));
        if (s_islast) g_count = 0;    // self-reset -> graph-replay deterministic
    }
    __syncthreads();
    if (!s_islast) return;

    double acc[5] = {0, 0, 0, 0, 0};
    for (int r = tid; r < nblocks; r += blockDim.x) {
        #pragma unroll
        for (int q = 0; q < 5; q++) acc[q] += g_part[r][q];
    }
    __shared__ double s_fin[5];
    if (tid < 5) s_fin[tid] = 0.0;
    __syncthreads();
    #pragma unroll
    for (int q = 0; q < 5; q++) {
        double v = warp_sumd(acc[q]);
        if (lane == 0 && v != 0.0) atomicAdd(&s_fin[q], v);
    }
    __syncthreads();
    if (tid == 0) {
        double n_obj = s_fin[0] < 1.0 ? 1.0 : s_fin[0];
        double cms   = s_fin[4] < 1.0 ? 1.0 : s_fin[4];
        const double balance = (l == 0) ? 0.4 : (l == 1 ? 1.0 : 4.0);
        const double obj_ratio = 5.0 * 608.0 * 608.0 / (416.0 * 416.0);
        double loss = s_fin[1] / n_obj * 0.05
                    + s_fin[3] / cms * balance * obj_ratio
                    + s_fin[2] / (n_obj * (double)NCLS);
        out[0] = (float)loss;
    }
}

extern "C" void kernel_launch(void* const* d_in, const int* in_sizes, int n_in,
                              void* d_out, int out_size)
{
    const float* inp  = (const float*)d_in[0];
    const float* tgt  = (const float*)d_in[1];
    const int*   lptr = (const int*)d_in[2];
    float* out = (float*)d_out;

    const int bs = in_sizes[0] / (255 * HW);        // 32
    const int blocks_x = (3 * HW / 4 + 127) / 128;  // 34

    yolo_fused<<<dim3(blocks_x, bs), 128>>>(inp, tgt, lptr, out);
}